// round 1
// baseline (speedup 1.0000x reference)
#include <cuda_runtime.h>
#include <cuda_bf16.h>
#include <cstdint>
#include <math.h>

#define Bb 4
#define Pp 2048
#define Dd 1024
#define Hh 16
#define KVh 8
#define HDh 64
#define Ff 4096
#define Ee 16
#define FEe 256
#define Tt (Bb*Pp)

// ---------------- scratch (device globals; no runtime allocation) ----------------
__device__ float g_h [(size_t)Tt*Dd];
__device__ float g_q [(size_t)Tt*Dd];
__device__ float g_k [(size_t)Tt*512];
__device__ float g_v [(size_t)Tt*512];
__device__ float g_o [(size_t)Tt*Dd];
__device__ float g_G1[(size_t)Tt*Ff];
__device__ float g_U1[(size_t)Tt*Ff];
__device__ float g_G2[(size_t)Tt*Ff];
__device__ float g_U2[(size_t)Tt*Ff];
__device__ float g_ct[Pp*32];
__device__ float g_st[Pp*32];

// ---------------- small helpers ----------------
__device__ __forceinline__ void cpa16(void* sm, const void* gp) {
    uint32_t s = (uint32_t)__cvta_generic_to_shared(sm);
    asm volatile("cp.async.cg.shared.global [%0], [%1], 16;\n" :: "r"(s), "l"(gp));
}
__device__ __forceinline__ void cp_commit() { asm volatile("cp.async.commit_group;\n"); }
__device__ __forceinline__ void cp_wait0()  { asm volatile("cp.async.wait_group 0;\n"); }

__device__ __forceinline__ uint32_t f2tf(float x) {
    uint32_t r;
    asm volatile("cvt.rna.tf32.f32 %0, %1;" : "=r"(r) : "f"(x));
    return r;
}
__device__ __forceinline__ void mma_tf32(float* c, const uint32_t* a, const uint32_t* b) {
    asm volatile(
        "mma.sync.aligned.m16n8k8.row.col.f32.tf32.tf32.f32 "
        "{%0,%1,%2,%3},{%4,%5,%6,%7},{%8,%9},{%0,%1,%2,%3};"
        : "+f"(c[0]), "+f"(c[1]), "+f"(c[2]), "+f"(c[3])
        : "r"(a[0]), "r"(a[1]), "r"(a[2]), "r"(a[3]), "r"(b[0]), "r"(b[1]));
}
__device__ __forceinline__ void mma_bf16(float* c, const uint32_t* a, const uint32_t* b) {
    asm volatile(
        "mma.sync.aligned.m16n8k16.row.col.f32.bf16.bf16.f32 "
        "{%0,%1,%2,%3},{%4,%5,%6,%7},{%8,%9},{%0,%1,%2,%3};"
        : "+f"(c[0]), "+f"(c[1]), "+f"(c[2]), "+f"(c[3])
        : "r"(a[0]), "r"(a[1]), "r"(a[2]), "r"(a[3]), "r"(b[0]), "r"(b[1]));
}
__device__ __forceinline__ uint32_t packbf(float a, float b) {
    __nv_bfloat162 t = __floats2bfloat162_rn(a, b);
    return *reinterpret_cast<uint32_t*>(&t);
}

// ---------------- RMSNorm ----------------
__global__ __launch_bounds__(256) void rmsnorm_k(const float* __restrict__ X,
                                                 const float* __restrict__ W,
                                                 float* __restrict__ Y) {
    int row = blockIdx.x;
    int tid = threadIdx.x;
    const float4* x4 = (const float4*)(X + (size_t)row * Dd);
    float4 v = x4[tid];
    float ss = v.x*v.x + v.y*v.y + v.z*v.z + v.w*v.w;
#pragma unroll
    for (int off = 16; off; off >>= 1) ss += __shfl_xor_sync(0xffffffffu, ss, off);
    __shared__ float red[8];
    if ((tid & 31) == 0) red[tid >> 5] = ss;
    __syncthreads();
    float tot = 0.f;
#pragma unroll
    for (int i = 0; i < 8; i++) tot += red[i];
    float s = rsqrtf(tot * (1.f / (float)Dd) + 1e-6f);
    const float4* w4 = (const float4*)W;
    float4 w = w4[tid];
    float4 o;
    o.x = v.x * s * w.x; o.y = v.y * s * w.y; o.z = v.z * s * w.z; o.w = v.w * s * w.w;
    ((float4*)(Y + (size_t)row * Dd))[tid] = o;
}

// ---------------- RoPE ----------------
__global__ void rope_table(float* __restrict__ ct, float* __restrict__ st) {
    int i = blockIdx.x * blockDim.x + threadIdx.x;   // Pp*32
    int p = i >> 5, j = i & 31;
    float expnt = (float)(2 * j) * (1.f / 64.f);
    float inv = powf(10000.f, -expnt);
    float ang = (float)p * inv;
    ct[i] = cosf(ang);
    st[i] = sinf(ang);
}
__global__ void rope_apply(float* __restrict__ x, const float* __restrict__ ct,
                           const float* __restrict__ st, int nh) {
    int i = blockIdx.x * blockDim.x + threadIdx.x;   // Tt*nh*32
    int j = i & 31;
    int hh = (i >> 5) % nh;
    int t = i / (32 * nh);
    int p = t & (Pp - 1);
    size_t base = (size_t)t * ((size_t)nh * 64) + (size_t)hh * 64 + j;
    float v1 = x[base], v2 = x[base + 32];
    float c = ct[p * 32 + j], s = st[p * 32 + j];
    x[base] = v1 * c - v2 * s;
    x[base + 32] = v2 * c + v1 * s;
}

// ---------------- GEMM: C[M,N] = A[M,K] @ B[K,N] (+bias, +add, +=C) ----------------
// BM=BN=128, BK=32, 256 threads, 8 warps (2M x 4N), warp tile 64x32, tf32 mma.
// estride!=0: expert-blocked B — column c maps to B + (c/FEe)*estride + k*ldb + (c%FEe)
#define AS_ST 36
#define BS_ST 136
#define GEMM_SMEM ((2*128*AS_ST + 2*32*BS_ST)*4)

__global__ __launch_bounds__(256) void gemm_tf32(
    const float* __restrict__ A, int lda,
    const float* __restrict__ B, int ldb, size_t estride,
    float* __restrict__ Dm, int ldd,
    const float* __restrict__ bias,
    const float* __restrict__ addsrc,
    int accum, int K) {
    extern __shared__ float smem[];
    float* As = smem;
    float* Bs = smem + 2 * 128 * AS_ST;
    const int tid = threadIdx.x;
    const int lane = tid & 31;
    const int g = lane >> 2, qd = lane & 3;
    const int warp = tid >> 5;
    const int wm = (warp >> 2) * 64;
    const int wn = (warp & 3) * 32;
    const int col0 = blockIdx.x * 128;
    const int row0 = blockIdx.y * 128;
    const float* Bt = estride ? (B + (size_t)(col0 / FEe) * estride + (col0 & (FEe - 1)))
                              : (B + col0);
    const float* At = A + (size_t)row0 * lda;

    float acc[4][4][4];
#pragma unroll
    for (int m = 0; m < 4; m++)
#pragma unroll
        for (int n = 0; n < 4; n++)
#pragma unroll
            for (int c = 0; c < 4; c++) acc[m][n][c] = 0.f;

    const int KT = K >> 5;

    auto issue = [&](int kt, int buf) {
        float* ab = As + buf * (128 * AS_ST);
#pragma unroll
        for (int i = 0; i < 4; i++) {
            int t = tid + i * 256;
            int r = t >> 3, c4 = (t & 7) << 2;
            cpa16(ab + r * AS_ST + c4, At + (size_t)r * lda + kt * 32 + c4);
        }
        float* bb = Bs + buf * (32 * BS_ST);
#pragma unroll
        for (int i = 0; i < 4; i++) {
            int t = tid + i * 256;
            int r = t >> 5, c4 = (t & 31) << 2;
            cpa16(bb + r * BS_ST + c4, Bt + (size_t)(kt * 32 + r) * ldb + c4);
        }
        cp_commit();
    };

    issue(0, 0);
    for (int kt = 0; kt < KT; ++kt) {
        cp_wait0();
        __syncthreads();
        if (kt + 1 < KT) issue(kt + 1, (kt + 1) & 1);
        const float* ab = As + (kt & 1) * (128 * AS_ST);
        const float* bb = Bs + (kt & 1) * (32 * BS_ST);
#pragma unroll
        for (int ks = 0; ks < 4; ++ks) {
            const int kb = ks * 8;
            uint32_t af[4][4];
#pragma unroll
            for (int m = 0; m < 4; m++) {
                const float* r0p = ab + (size_t)(wm + m * 16 + g) * AS_ST + kb + qd;
                af[m][0] = f2tf(r0p[0]);
                af[m][1] = f2tf(r0p[8 * AS_ST]);
                af[m][2] = f2tf(r0p[4]);
                af[m][3] = f2tf(r0p[8 * AS_ST + 4]);
            }
            uint32_t bfr[4][2];
#pragma unroll
            for (int n = 0; n < 4; n++) {
                const float* bp = bb + (size_t)(kb + qd) * BS_ST + wn + n * 8 + g;
                bfr[n][0] = f2tf(bp[0]);
                bfr[n][1] = f2tf(bp[4 * BS_ST]);
            }
#pragma unroll
            for (int m = 0; m < 4; m++)
#pragma unroll
                for (int n = 0; n < 4; n++)
                    mma_tf32(acc[m][n], af[m], bfr[n]);
        }
        __syncthreads();
    }

    // epilogue
#pragma unroll
    for (int m = 0; m < 4; m++) {
        int r0 = row0 + wm + m * 16 + g;
#pragma unroll
        for (int n = 0; n < 4; n++) {
            int c = col0 + wn + n * 8 + 2 * qd;
#pragma unroll
            for (int half = 0; half < 2; half++) {
                int r = r0 + half * 8;
                float v0 = acc[m][n][half * 2], v1 = acc[m][n][half * 2 + 1];
                size_t o0 = (size_t)r * ldd + c;
                if (bias)   { v0 += bias[c];       v1 += bias[c + 1]; }
                if (addsrc) { v0 += addsrc[o0];    v1 += addsrc[o0 + 1]; }
                if (accum)  { v0 += Dm[o0];        v1 += Dm[o0 + 1]; }
                Dm[o0] = v0; Dm[o0 + 1] = v1;
            }
        }
    }
}

// ---------------- Flash attention (causal, GQA rep=2) ----------------
// grid (Pp/128, Bb*Hh), 256 threads. Q tile 128x64, K/V tiles 128x64 double-buffered.
// S via tf32 mma (16 n-frags/warp), online softmax, PV via bf16 mma (reg P trick).
#define KS_ST 68
#define FLASH_SMEM (5 * 128 * KS_ST * 4)

__global__ __launch_bounds__(256) void flash_attn(const float* __restrict__ Q,
                                                  const float* __restrict__ Kg,
                                                  const float* __restrict__ Vg,
                                                  float* __restrict__ O) {
    extern __shared__ float smem[];
    float* Qs = smem;                        // [128][68]
    float* Ks = smem + 128 * KS_ST;          // [2][128][68]
    float* Vs = Ks + 2 * 128 * KS_ST;        // [2][128][68]
    const int tid = threadIdx.x;
    const int lane = tid & 31;
    const int g = lane >> 2, qd = lane & 3;
    const int warp = tid >> 5;
    const int wr0 = warp * 16;
    const int bh = blockIdx.y;
    const int b = bh >> 4, h = bh & 15, kvh = h >> 1;
    const int qt = blockIdx.x;
    const int row0 = qt * 128;
    const float* Qb = Q + (size_t)(b * Pp + row0) * (Hh * HDh) + h * HDh;
    const float* Kb = Kg + (size_t)(b * Pp) * (KVh * HDh) + kvh * HDh;
    const float* Vb = Vg + (size_t)(b * Pp) * (KVh * HDh) + kvh * HDh;

    // Q tile
#pragma unroll
    for (int i = 0; i < 8; i++) {
        int t = tid + i * 256;
        int r = t >> 4, c4 = (t & 15) << 2;
        cpa16(Qs + r * KS_ST + c4, Qb + (size_t)r * (Hh * HDh) + c4);
    }
    auto issueKV = [&](int kt, int buf) {
        float* ks = Ks + buf * (128 * KS_ST);
        float* vs = Vs + buf * (128 * KS_ST);
#pragma unroll
        for (int i = 0; i < 8; i++) {
            int t = tid + i * 256;
            int r = t >> 4, c4 = (t & 15) << 2;
            cpa16(ks + r * KS_ST + c4, Kb + (size_t)(kt * 128 + r) * (KVh * HDh) + c4);
        }
#pragma unroll
        for (int i = 0; i < 8; i++) {
            int t = tid + i * 256;
            int r = t >> 4, c4 = (t & 15) << 2;
            cpa16(vs + r * KS_ST + c4, Vb + (size_t)(kt * 128 + r) * (KVh * HDh) + c4);
        }
        cp_commit();
    };
    issueKV(0, 0);  // commits Q + K0 + V0 together

    float m0 = -INFINITY, m1 = -INFINITY, l0 = 0.f, l1 = 0.f;
    float oacc[8][4];
#pragma unroll
    for (int n = 0; n < 8; n++)
#pragma unroll
        for (int c = 0; c < 4; c++) oacc[n][c] = 0.f;

    const int nkt = qt + 1;
    for (int kt = 0; kt < nkt; ++kt) {
        cp_wait0();
        __syncthreads();
        if (kt + 1 < nkt) issueKV(kt + 1, (kt + 1) & 1);
        const float* ks = Ks + (kt & 1) * (128 * KS_ST);
        const float* vs = Vs + (kt & 1) * (128 * KS_ST);

        float sacc[16][4];
#pragma unroll
        for (int n = 0; n < 16; n++)
#pragma unroll
            for (int c = 0; c < 4; c++) sacc[n][c] = 0.f;

#pragma unroll
        for (int kk = 0; kk < 8; ++kk) {
            const int kb = kk * 8;
            uint32_t aq[4];
            {
                const float* r0p = Qs + (size_t)(wr0 + g) * KS_ST + kb + qd;
                aq[0] = f2tf(r0p[0]);
                aq[1] = f2tf(r0p[8 * KS_ST]);
                aq[2] = f2tf(r0p[4]);
                aq[3] = f2tf(r0p[8 * KS_ST + 4]);
            }
#pragma unroll
            for (int nf = 0; nf < 16; nf++) {
                const float* bp = ks + (size_t)(nf * 8 + g) * KS_ST + kb + qd;
                uint32_t bb[2];
                bb[0] = f2tf(bp[0]);
                bb[1] = f2tf(bp[4]);
                mma_tf32(sacc[nf], aq, bb);
            }
        }

        // scale + causal mask
        const bool diag = (kt == qt);
#pragma unroll
        for (int nf = 0; nf < 16; nf++) {
#pragma unroll
            for (int c = 0; c < 4; c++) {
                float v = sacc[nf][c] * 0.125f;
                if (diag) {
                    int colL = nf * 8 + 2 * qd + (c & 1);
                    int rowL = wr0 + g + ((c >= 2) ? 8 : 0);
                    if (colL > rowL) v = -1e30f;
                }
                sacc[nf][c] = v;
            }
        }
        // row maxes (rows g and g+8)
        float rm0 = -1e30f, rm1 = -1e30f;
#pragma unroll
        for (int nf = 0; nf < 16; nf++) {
            rm0 = fmaxf(rm0, fmaxf(sacc[nf][0], sacc[nf][1]));
            rm1 = fmaxf(rm1, fmaxf(sacc[nf][2], sacc[nf][3]));
        }
        rm0 = fmaxf(rm0, __shfl_xor_sync(0xffffffffu, rm0, 1));
        rm0 = fmaxf(rm0, __shfl_xor_sync(0xffffffffu, rm0, 2));
        rm1 = fmaxf(rm1, __shfl_xor_sync(0xffffffffu, rm1, 1));
        rm1 = fmaxf(rm1, __shfl_xor_sync(0xffffffffu, rm1, 2));
        float mn0 = fmaxf(m0, rm0), mn1 = fmaxf(m1, rm1);
        float sc0 = __expf(m0 - mn0), sc1 = __expf(m1 - mn1);
        float rs0 = 0.f, rs1 = 0.f;
#pragma unroll
        for (int nf = 0; nf < 16; nf++) {
            float p0 = __expf(sacc[nf][0] - mn0);
            float p1 = __expf(sacc[nf][1] - mn0);
            float p2 = __expf(sacc[nf][2] - mn1);
            float p3 = __expf(sacc[nf][3] - mn1);
            sacc[nf][0] = p0; sacc[nf][1] = p1; sacc[nf][2] = p2; sacc[nf][3] = p3;
            rs0 += p0 + p1; rs1 += p2 + p3;
        }
        rs0 += __shfl_xor_sync(0xffffffffu, rs0, 1);
        rs0 += __shfl_xor_sync(0xffffffffu, rs0, 2);
        rs1 += __shfl_xor_sync(0xffffffffu, rs1, 1);
        rs1 += __shfl_xor_sync(0xffffffffu, rs1, 2);
        l0 = l0 * sc0 + rs0;
        l1 = l1 * sc1 + rs1;
        m0 = mn0; m1 = mn1;
#pragma unroll
        for (int n = 0; n < 8; n++) {
            oacc[n][0] *= sc0; oacc[n][1] *= sc0;
            oacc[n][2] *= sc1; oacc[n][3] *= sc1;
        }
        // PV: P (regs -> bf16) @ V
#pragma unroll
        for (int j = 0; j < 8; j++) {
            uint32_t pa[4];
            pa[0] = packbf(sacc[2 * j][0], sacc[2 * j][1]);
            pa[1] = packbf(sacc[2 * j][2], sacc[2 * j][3]);
            pa[2] = packbf(sacc[2 * j + 1][0], sacc[2 * j + 1][1]);
            pa[3] = packbf(sacc[2 * j + 1][2], sacc[2 * j + 1][3]);
#pragma unroll
            for (int nf = 0; nf < 8; nf++) {
                const float* vp = vs + (size_t)(16 * j + 2 * qd) * KS_ST + nf * 8 + g;
                uint32_t vb[2];
                vb[0] = packbf(vp[0], vp[KS_ST]);
                vb[1] = packbf(vp[8 * KS_ST], vp[9 * KS_ST]);
                mma_bf16(oacc[nf], pa, vb);
            }
        }
        __syncthreads();
    }

    float inv0 = 1.f / l0, inv1 = 1.f / l1;
#pragma unroll
    for (int nf = 0; nf < 8; nf++) {
        size_t base = (size_t)(b * Pp + row0 + wr0 + g) * (Hh * HDh) + h * HDh + nf * 8 + 2 * qd;
        O[base] = oacc[nf][0] * inv0;
        O[base + 1] = oacc[nf][1] * inv0;
        size_t base2 = base + (size_t)8 * (Hh * HDh);
        O[base2] = oacc[nf][2] * inv1;
        O[base2 + 1] = oacc[nf][3] * inv1;
    }
}

// ---------------- activations ----------------
__global__ __launch_bounds__(256) void act_base(float* __restrict__ G, const float* __restrict__ U) {
    size_t i = (size_t)blockIdx.x * blockDim.x + threadIdx.x;  // over Tt*Ff/4
    float4 gv = ((float4*)G)[i];
    float4 uv = ((const float4*)U)[i];
    gv.x = gv.x / (1.f + __expf(-gv.x)) * uv.x;
    gv.y = gv.y / (1.f + __expf(-gv.y)) * uv.y;
    gv.z = gv.z / (1.f + __expf(-gv.z)) * uv.z;
    gv.w = gv.w / (1.f + __expf(-gv.w)) * uv.w;
    ((float4*)G)[i] = gv;
}
__global__ __launch_bounds__(256) void act_expert(float* __restrict__ G, const float* __restrict__ U,
                                                  const float* __restrict__ M) {
    size_t i = (size_t)blockIdx.x * blockDim.x + threadIdx.x;  // over Tt*Ff/4
    size_t col4 = i & 1023;        // Ff/4 = 1024 float4 per row
    size_t t = i >> 10;
    int e = (int)(col4 >> 6);      // 64 float4 per expert chunk (FEe=256)
    float mk = M[t * Ee + e];
    float4 gv = ((float4*)G)[i];
    float4 uv = ((const float4*)U)[i];
    gv.x = mk * (gv.x / (1.f + __expf(-gv.x))) * uv.x;
    gv.y = mk * (gv.y / (1.f + __expf(-gv.y))) * uv.y;
    gv.z = mk * (gv.z / (1.f + __expf(-gv.z))) * uv.z;
    gv.w = mk * (gv.w / (1.f + __expf(-gv.w))) * uv.w;
    ((float4*)G)[i] = gv;
}

// ---------------- launch ----------------
extern "C" void kernel_launch(void* const* d_in, const int* in_sizes, int n_in,
                              void* d_out, int out_size) {
    const float* x     = (const float*)d_in[0];
    const float* emask = (const float*)d_in[1];
    const float* ln1   = (const float*)d_in[2];
    const float* wq    = (const float*)d_in[3];
    const float* bq    = (const float*)d_in[4];
    const float* wk    = (const float*)d_in[5];
    const float* bk    = (const float*)d_in[6];
    const float* wv    = (const float*)d_in[7];
    const float* bv    = (const float*)d_in[8];
    const float* wo    = (const float*)d_in[9];
    const float* ln2   = (const float*)d_in[10];
    const float* wgate = (const float*)d_in[11];
    const float* wup   = (const float*)d_in[12];
    const float* wdown = (const float*)d_in[13];
    const float* weg   = (const float*)d_in[14];
    const float* weu   = (const float*)d_in[15];
    const float* wed   = (const float*)d_in[16];
    float* out = (float*)d_out;

    float *h, *q, *k, *v, *o, *G1, *U1, *G2, *U2, *ct, *st;
    cudaGetSymbolAddress((void**)&h,  g_h);
    cudaGetSymbolAddress((void**)&q,  g_q);
    cudaGetSymbolAddress((void**)&k,  g_k);
    cudaGetSymbolAddress((void**)&v,  g_v);
    cudaGetSymbolAddress((void**)&o,  g_o);
    cudaGetSymbolAddress((void**)&G1, g_G1);
    cudaGetSymbolAddress((void**)&U1, g_U1);
    cudaGetSymbolAddress((void**)&G2, g_G2);
    cudaGetSymbolAddress((void**)&U2, g_U2);
    cudaGetSymbolAddress((void**)&ct, g_ct);
    cudaGetSymbolAddress((void**)&st, g_st);

    cudaFuncSetAttribute(gemm_tf32, cudaFuncAttributeMaxDynamicSharedMemorySize, GEMM_SMEM);
    cudaFuncSetAttribute(flash_attn, cudaFuncAttributeMaxDynamicSharedMemorySize, FLASH_SMEM);

    // 1) h = rmsnorm(x)
    rmsnorm_k<<<Tt, 256>>>(x, ln1, h);
    // 2) q,k,v projections (+bias)
    gemm_tf32<<<dim3(Dd / 128, Tt / 128), 256, GEMM_SMEM>>>(h, Dd, wq, Hh * HDh, 0, q, Hh * HDh, bq, nullptr, 0, Dd);
    gemm_tf32<<<dim3(512 / 128, Tt / 128), 256, GEMM_SMEM>>>(h, Dd, wk, KVh * HDh, 0, k, KVh * HDh, bk, nullptr, 0, Dd);
    gemm_tf32<<<dim3(512 / 128, Tt / 128), 256, GEMM_SMEM>>>(h, Dd, wv, KVh * HDh, 0, v, KVh * HDh, bv, nullptr, 0, Dd);
    // 3) RoPE
    rope_table<<<(Pp * 32) / 256, 256>>>(ct, st);
    rope_apply<<<(Tt * Hh * 32) / 256, 256>>>(q, ct, st, Hh);
    rope_apply<<<(Tt * KVh * 32) / 256, 256>>>(k, ct, st, KVh);
    // 4) causal GQA flash attention
    flash_attn<<<dim3(Pp / 128, Bb * Hh), 256, FLASH_SMEM>>>(q, k, v, o);
    // 5) out = o @ wo + x   (xo residual lives in d_out)
    gemm_tf32<<<dim3(Dd / 128, Tt / 128), 256, GEMM_SMEM>>>(o, Hh * HDh, wo, Dd, 0, out, Dd, nullptr, x, 0, Hh * HDh);
    // 6) h2 = rmsnorm(xo)
    rmsnorm_k<<<Tt, 256>>>(out, ln2, h);
    // 7) dense MLP + expert gate/up GEMMs
    gemm_tf32<<<dim3(Ff / 128, Tt / 128), 256, GEMM_SMEM>>>(h, Dd, wgate, Ff, 0, G1, Ff, nullptr, nullptr, 0, Dd);
    gemm_tf32<<<dim3(Ff / 128, Tt / 128), 256, GEMM_SMEM>>>(h, Dd, wup,   Ff, 0, U1, Ff, nullptr, nullptr, 0, Dd);
    gemm_tf32<<<dim3(Ff / 128, Tt / 128), 256, GEMM_SMEM>>>(h, Dd, weg, FEe, (size_t)Dd * FEe, G2, Ff, nullptr, nullptr, 0, Dd);
    gemm_tf32<<<dim3(Ff / 128, Tt / 128), 256, GEMM_SMEM>>>(h, Dd, weu, FEe, (size_t)Dd * FEe, U2, Ff, nullptr, nullptr, 0, Dd);
    // 8) activations (in-place into G1/G2; expert one folds the routing mask)
    act_base<<<((size_t)Tt * Ff / 4) / 256, 256>>>(G1, U1);
    act_expert<<<((size_t)Tt * Ff / 4) / 256, 256>>>(G2, U2, emask);
    // 9) out += act_b @ w_down ; out += act_e @ we_down_flat
    gemm_tf32<<<dim3(Dd / 128, Tt / 128), 256, GEMM_SMEM>>>(G1, Ff, wdown, Dd, 0, out, Dd, nullptr, nullptr, 1, Ff);
    gemm_tf32<<<dim3(Dd / 128, Tt / 128), 256, GEMM_SMEM>>>(G2, Ff, wed,   Dd, 0, out, Dd, nullptr, nullptr, 1, Ff);
}

// round 2
// speedup vs baseline: 1.1782x; 1.1782x over previous
#include <cuda_runtime.h>
#include <cuda_bf16.h>
#include <cstdint>
#include <math.h>

#define Bb 4
#define Pp 2048
#define Dd 1024
#define Hh 16
#define KVh 8
#define HDh 64
#define Ff 4096
#define Ee 16
#define FEe 256
#define Tt (Bb*Pp)

// compensation for tf32 truncation bias (two operands, mantissa-uniform model)
#define TF32_COMP 1.000704f

// ---------------- scratch (device globals; no runtime allocation) ----------------
__device__ float g_h [(size_t)Tt*Dd];
__device__ float g_q [(size_t)Tt*Dd];
__device__ float g_k [(size_t)Tt*512];
__device__ float g_v [(size_t)Tt*512];
__device__ float g_o [(size_t)Tt*Dd];
__device__ float g_G1[(size_t)Tt*Ff];
__device__ float g_U1[(size_t)Tt*Ff];
__device__ float g_G2[(size_t)Tt*Ff];
__device__ float g_U2[(size_t)Tt*Ff];
__device__ float g_ct[Pp*32];
__device__ float g_st[Pp*32];

// ---------------- small helpers ----------------
__device__ __forceinline__ void cpa16(void* sm, const void* gp) {
    uint32_t s = (uint32_t)__cvta_generic_to_shared(sm);
    asm volatile("cp.async.cg.shared.global [%0], [%1], 16;\n" :: "r"(s), "l"(gp));
}
__device__ __forceinline__ void cp_commit() { asm volatile("cp.async.commit_group;\n"); }
__device__ __forceinline__ void cp_wait0()  { asm volatile("cp.async.wait_group 0;\n"); }

// raw fp32 bits fed to tf32 mma (HW truncates mantissa; bias compensated in epilogue)
__device__ __forceinline__ uint32_t f2u(float x) { return __float_as_uint(x); }

__device__ __forceinline__ void mma_tf32(float* c, const uint32_t* a, const uint32_t* b) {
    asm volatile(
        "mma.sync.aligned.m16n8k8.row.col.f32.tf32.tf32.f32 "
        "{%0,%1,%2,%3},{%4,%5,%6,%7},{%8,%9},{%0,%1,%2,%3};"
        : "+f"(c[0]), "+f"(c[1]), "+f"(c[2]), "+f"(c[3])
        : "r"(a[0]), "r"(a[1]), "r"(a[2]), "r"(a[3]), "r"(b[0]), "r"(b[1]));
}
__device__ __forceinline__ void mma_bf16(float* c, const uint32_t* a, const uint32_t* b) {
    asm volatile(
        "mma.sync.aligned.m16n8k16.row.col.f32.bf16.bf16.f32 "
        "{%0,%1,%2,%3},{%4,%5,%6,%7},{%8,%9},{%0,%1,%2,%3};"
        : "+f"(c[0]), "+f"(c[1]), "+f"(c[2]), "+f"(c[3])
        : "r"(a[0]), "r"(a[1]), "r"(a[2]), "r"(a[3]), "r"(b[0]), "r"(b[1]));
}
__device__ __forceinline__ uint32_t packbf(float a, float b) {
    __nv_bfloat162 t = __floats2bfloat162_rn(a, b);
    return *reinterpret_cast<uint32_t*>(&t);
}

// ---------------- RMSNorm ----------------
__global__ __launch_bounds__(256) void rmsnorm_k(const float* __restrict__ X,
                                                 const float* __restrict__ W,
                                                 float* __restrict__ Y) {
    int row = blockIdx.x;
    int tid = threadIdx.x;
    const float4* x4 = (const float4*)(X + (size_t)row * Dd);
    float4 v = x4[tid];
    float ss = v.x*v.x + v.y*v.y + v.z*v.z + v.w*v.w;
#pragma unroll
    for (int off = 16; off; off >>= 1) ss += __shfl_xor_sync(0xffffffffu, ss, off);
    __shared__ float red[8];
    if ((tid & 31) == 0) red[tid >> 5] = ss;
    __syncthreads();
    float tot = 0.f;
#pragma unroll
    for (int i = 0; i < 8; i++) tot += red[i];
    float s = rsqrtf(tot * (1.f / (float)Dd) + 1e-6f);
    const float4* w4 = (const float4*)W;
    float4 w = w4[tid];
    float4 o;
    o.x = v.x * s * w.x; o.y = v.y * s * w.y; o.z = v.z * s * w.z; o.w = v.w * s * w.w;
    ((float4*)(Y + (size_t)row * Dd))[tid] = o;
}

// ---------------- RoPE ----------------
__global__ void rope_table(float* __restrict__ ct, float* __restrict__ st) {
    int i = blockIdx.x * blockDim.x + threadIdx.x;   // Pp*32
    int p = i >> 5, j = i & 31;
    float expnt = (float)(2 * j) * (1.f / 64.f);
    float inv = powf(10000.f, -expnt);
    float ang = (float)p * inv;
    ct[i] = cosf(ang);
    st[i] = sinf(ang);
}
__global__ void rope_apply(float* __restrict__ x, const float* __restrict__ ct,
                           const float* __restrict__ st, int nh) {
    int i = blockIdx.x * blockDim.x + threadIdx.x;   // Tt*nh*32
    int j = i & 31;
    int hh = (i >> 5) % nh;
    int t = i / (32 * nh);
    int p = t & (Pp - 1);
    size_t base = (size_t)t * ((size_t)nh * 64) + (size_t)hh * 64 + j;
    float v1 = x[base], v2 = x[base + 32];
    float c = ct[p * 32 + j], s = st[p * 32 + j];
    x[base] = v1 * c - v2 * s;
    x[base + 32] = v2 * c + v1 * s;
}

// ---------------- GEMM: C[M,N] = A[M,K] @ B[K,N] (+bias, +add, +=C) ----------------
// BM=BN=128, BK=32, 256 threads, 8 warps (2M x 4N), warp tile 64x32, tf32 mma.
// estride!=0: expert-blocked B — column c maps to B + (c/FEe)*estride + k*ldb + (c%FEe)
#define AS_ST 36
#define BS_ST 136
#define GEMM_SMEM ((2*128*AS_ST + 2*32*BS_ST)*4)

__global__ __launch_bounds__(256) void gemm_tf32(
    const float* __restrict__ A, int lda,
    const float* __restrict__ B, int ldb, size_t estride,
    float* __restrict__ Dm, int ldd,
    const float* __restrict__ bias,
    const float* __restrict__ addsrc,
    int accum, int K) {
    extern __shared__ float smem[];
    float* As = smem;
    float* Bs = smem + 2 * 128 * AS_ST;
    const int tid = threadIdx.x;
    const int lane = tid & 31;
    const int g = lane >> 2, qd = lane & 3;
    const int warp = tid >> 5;
    const int wm = (warp >> 2) * 64;
    const int wn = (warp & 3) * 32;
    const int col0 = blockIdx.x * 128;
    const int row0 = blockIdx.y * 128;
    const float* Bt = estride ? (B + (size_t)(col0 / FEe) * estride + (col0 & (FEe - 1)))
                              : (B + col0);
    const float* At = A + (size_t)row0 * lda;

    float acc[4][4][4];
#pragma unroll
    for (int m = 0; m < 4; m++)
#pragma unroll
        for (int n = 0; n < 4; n++)
#pragma unroll
            for (int c = 0; c < 4; c++) acc[m][n][c] = 0.f;

    const int KT = K >> 5;

    auto issue = [&](int kt, int buf) {
        float* ab = As + buf * (128 * AS_ST);
#pragma unroll
        for (int i = 0; i < 4; i++) {
            int t = tid + i * 256;
            int r = t >> 3, c4 = (t & 7) << 2;
            cpa16(ab + r * AS_ST + c4, At + (size_t)r * lda + kt * 32 + c4);
        }
        float* bb = Bs + buf * (32 * BS_ST);
#pragma unroll
        for (int i = 0; i < 4; i++) {
            int t = tid + i * 256;
            int r = t >> 5, c4 = (t & 31) << 2;
            cpa16(bb + r * BS_ST + c4, Bt + (size_t)(kt * 32 + r) * ldb + c4);
        }
        cp_commit();
    };

    issue(0, 0);
    for (int kt = 0; kt < KT; ++kt) {
        cp_wait0();
        __syncthreads();
        if (kt + 1 < KT) issue(kt + 1, (kt + 1) & 1);
        const float* ab = As + (kt & 1) * (128 * AS_ST);
        const float* bb = Bs + (kt & 1) * (32 * BS_ST);
#pragma unroll
        for (int ks = 0; ks < 4; ++ks) {
            const int kb = ks * 8;
            uint32_t af[4][4];
#pragma unroll
            for (int m = 0; m < 4; m++) {
                const float* r0p = ab + (size_t)(wm + m * 16 + g) * AS_ST + kb + qd;
                af[m][0] = f2u(r0p[0]);
                af[m][1] = f2u(r0p[8 * AS_ST]);
                af[m][2] = f2u(r0p[4]);
                af[m][3] = f2u(r0p[8 * AS_ST + 4]);
            }
            uint32_t bfr[4][2];
#pragma unroll
            for (int n = 0; n < 4; n++) {
                const float* bp = bb + (size_t)(kb + qd) * BS_ST + wn + n * 8 + g;
                bfr[n][0] = f2u(bp[0]);
                bfr[n][1] = f2u(bp[4 * BS_ST]);
            }
#pragma unroll
            for (int m = 0; m < 4; m++)
#pragma unroll
                for (int n = 0; n < 4; n++)
                    mma_tf32(acc[m][n], af[m], bfr[n]);
        }
        __syncthreads();
    }

    // epilogue (TF32_COMP cancels truncation bias of the mma accumulation)
#pragma unroll
    for (int m = 0; m < 4; m++) {
        int r0 = row0 + wm + m * 16 + g;
#pragma unroll
        for (int n = 0; n < 4; n++) {
            int c = col0 + wn + n * 8 + 2 * qd;
#pragma unroll
            for (int half = 0; half < 2; half++) {
                int r = r0 + half * 8;
                float v0 = acc[m][n][half * 2] * TF32_COMP;
                float v1 = acc[m][n][half * 2 + 1] * TF32_COMP;
                size_t o0 = (size_t)r * ldd + c;
                if (bias)   { v0 += bias[c];       v1 += bias[c + 1]; }
                if (addsrc) { v0 += addsrc[o0];    v1 += addsrc[o0 + 1]; }
                if (accum)  { v0 += Dm[o0];        v1 += Dm[o0 + 1]; }
                Dm[o0] = v0; Dm[o0 + 1] = v1;
            }
        }
    }
}

// ---------------- Flash attention (causal, GQA rep=2) ----------------
// grid (Pp/128, Bb*Hh), 256 threads. Q tile 128x64, K/V tiles 128x64 double-buffered.
// S via tf32 mma (raw-bit truncation: acts as tiny softmax temperature, harmless),
// online softmax, PV via bf16 mma (reg P trick).
#define KS_ST 68
#define FLASH_SMEM (5 * 128 * KS_ST * 4)

__global__ __launch_bounds__(256) void flash_attn(const float* __restrict__ Q,
                                                  const float* __restrict__ Kg,
                                                  const float* __restrict__ Vg,
                                                  float* __restrict__ O) {
    extern __shared__ float smem[];
    float* Qs = smem;                        // [128][68]
    float* Ks = smem + 128 * KS_ST;          // [2][128][68]
    float* Vs = Ks + 2 * 128 * KS_ST;        // [2][128][68]
    const int tid = threadIdx.x;
    const int lane = tid & 31;
    const int g = lane >> 2, qd = lane & 3;
    const int warp = tid >> 5;
    const int wr0 = warp * 16;
    const int bh = blockIdx.y;
    const int b = bh >> 4, h = bh & 15, kvh = h >> 1;
    const int qt = blockIdx.x;
    const int row0 = qt * 128;
    const float* Qb = Q + (size_t)(b * Pp + row0) * (Hh * HDh) + h * HDh;
    const float* Kb = Kg + (size_t)(b * Pp) * (KVh * HDh) + kvh * HDh;
    const float* Vb = Vg + (size_t)(b * Pp) * (KVh * HDh) + kvh * HDh;

    // Q tile
#pragma unroll
    for (int i = 0; i < 8; i++) {
        int t = tid + i * 256;
        int r = t >> 4, c4 = (t & 15) << 2;
        cpa16(Qs + r * KS_ST + c4, Qb + (size_t)r * (Hh * HDh) + c4);
    }
    auto issueKV = [&](int kt, int buf) {
        float* ks = Ks + buf * (128 * KS_ST);
        float* vs = Vs + buf * (128 * KS_ST);
#pragma unroll
        for (int i = 0; i < 8; i++) {
            int t = tid + i * 256;
            int r = t >> 4, c4 = (t & 15) << 2;
            cpa16(ks + r * KS_ST + c4, Kb + (size_t)(kt * 128 + r) * (KVh * HDh) + c4);
        }
#pragma unroll
        for (int i = 0; i < 8; i++) {
            int t = tid + i * 256;
            int r = t >> 4, c4 = (t & 15) << 2;
            cpa16(vs + r * KS_ST + c4, Vb + (size_t)(kt * 128 + r) * (KVh * HDh) + c4);
        }
        cp_commit();
    };
    issueKV(0, 0);  // commits Q + K0 + V0 together

    float m0 = -INFINITY, m1 = -INFINITY, l0 = 0.f, l1 = 0.f;
    float oacc[8][4];
#pragma unroll
    for (int n = 0; n < 8; n++)
#pragma unroll
        for (int c = 0; c < 4; c++) oacc[n][c] = 0.f;

    const int nkt = qt + 1;
    for (int kt = 0; kt < nkt; ++kt) {
        cp_wait0();
        __syncthreads();
        if (kt + 1 < nkt) issueKV(kt + 1, (kt + 1) & 1);
        const float* ks = Ks + (kt & 1) * (128 * KS_ST);
        const float* vs = Vs + (kt & 1) * (128 * KS_ST);

        float sacc[16][4];
#pragma unroll
        for (int n = 0; n < 16; n++)
#pragma unroll
            for (int c = 0; c < 4; c++) sacc[n][c] = 0.f;

#pragma unroll
        for (int kk = 0; kk < 8; ++kk) {
            const int kb = kk * 8;
            uint32_t aq[4];
            {
                const float* r0p = Qs + (size_t)(wr0 + g) * KS_ST + kb + qd;
                aq[0] = f2u(r0p[0]);
                aq[1] = f2u(r0p[8 * KS_ST]);
                aq[2] = f2u(r0p[4]);
                aq[3] = f2u(r0p[8 * KS_ST + 4]);
            }
#pragma unroll
            for (int nf = 0; nf < 16; nf++) {
                const float* bp = ks + (size_t)(nf * 8 + g) * KS_ST + kb + qd;
                uint32_t bb[2];
                bb[0] = f2u(bp[0]);
                bb[1] = f2u(bp[4]);
                mma_tf32(sacc[nf], aq, bb);
            }
        }

        // scale + causal mask
        const bool diag = (kt == qt);
#pragma unroll
        for (int nf = 0; nf < 16; nf++) {
#pragma unroll
            for (int c = 0; c < 4; c++) {
                float v = sacc[nf][c] * 0.125f;
                if (diag) {
                    int colL = nf * 8 + 2 * qd + (c & 1);
                    int rowL = wr0 + g + ((c >= 2) ? 8 : 0);
                    if (colL > rowL) v = -1e30f;
                }
                sacc[nf][c] = v;
            }
        }
        // row maxes (rows g and g+8)
        float rm0 = -1e30f, rm1 = -1e30f;
#pragma unroll
        for (int nf = 0; nf < 16; nf++) {
            rm0 = fmaxf(rm0, fmaxf(sacc[nf][0], sacc[nf][1]));
            rm1 = fmaxf(rm1, fmaxf(sacc[nf][2], sacc[nf][3]));
        }
        rm0 = fmaxf(rm0, __shfl_xor_sync(0xffffffffu, rm0, 1));
        rm0 = fmaxf(rm0, __shfl_xor_sync(0xffffffffu, rm0, 2));
        rm1 = fmaxf(rm1, __shfl_xor_sync(0xffffffffu, rm1, 1));
        rm1 = fmaxf(rm1, __shfl_xor_sync(0xffffffffu, rm1, 2));
        float mn0 = fmaxf(m0, rm0), mn1 = fmaxf(m1, rm1);
        float sc0 = __expf(m0 - mn0), sc1 = __expf(m1 - mn1);
        float rs0 = 0.f, rs1 = 0.f;
#pragma unroll
        for (int nf = 0; nf < 16; nf++) {
            float p0 = __expf(sacc[nf][0] - mn0);
            float p1 = __expf(sacc[nf][1] - mn0);
            float p2 = __expf(sacc[nf][2] - mn1);
            float p3 = __expf(sacc[nf][3] - mn1);
            sacc[nf][0] = p0; sacc[nf][1] = p1; sacc[nf][2] = p2; sacc[nf][3] = p3;
            rs0 += p0 + p1; rs1 += p2 + p3;
        }
        rs0 += __shfl_xor_sync(0xffffffffu, rs0, 1);
        rs0 += __shfl_xor_sync(0xffffffffu, rs0, 2);
        rs1 += __shfl_xor_sync(0xffffffffu, rs1, 1);
        rs1 += __shfl_xor_sync(0xffffffffu, rs1, 2);
        l0 = l0 * sc0 + rs0;
        l1 = l1 * sc1 + rs1;
        m0 = mn0; m1 = mn1;
#pragma unroll
        for (int n = 0; n < 8; n++) {
            oacc[n][0] *= sc0; oacc[n][1] *= sc0;
            oacc[n][2] *= sc1; oacc[n][3] *= sc1;
        }
        // PV: P (regs -> bf16) @ V
#pragma unroll
        for (int j = 0; j < 8; j++) {
            uint32_t pa[4];
            pa[0] = packbf(sacc[2 * j][0], sacc[2 * j][1]);
            pa[1] = packbf(sacc[2 * j][2], sacc[2 * j][3]);
            pa[2] = packbf(sacc[2 * j + 1][0], sacc[2 * j + 1][1]);
            pa[3] = packbf(sacc[2 * j + 1][2], sacc[2 * j + 1][3]);
#pragma unroll
            for (int nf = 0; nf < 8; nf++) {
                const float* vp = vs + (size_t)(16 * j + 2 * qd) * KS_ST + nf * 8 + g;
                uint32_t vb[2];
                vb[0] = packbf(vp[0], vp[KS_ST]);
                vb[1] = packbf(vp[8 * KS_ST], vp[9 * KS_ST]);
                mma_bf16(oacc[nf], pa, vb);
            }
        }
        __syncthreads();
    }

    float inv0 = 1.f / l0, inv1 = 1.f / l1;
#pragma unroll
    for (int nf = 0; nf < 8; nf++) {
        size_t base = (size_t)(b * Pp + row0 + wr0 + g) * (Hh * HDh) + h * HDh + nf * 8 + 2 * qd;
        O[base] = oacc[nf][0] * inv0;
        O[base + 1] = oacc[nf][1] * inv0;
        size_t base2 = base + (size_t)8 * (Hh * HDh);
        O[base2] = oacc[nf][2] * inv1;
        O[base2 + 1] = oacc[nf][3] * inv1;
    }
}

// ---------------- activations ----------------
__global__ __launch_bounds__(256) void act_base(float* __restrict__ G, const float* __restrict__ U) {
    size_t i = (size_t)blockIdx.x * blockDim.x + threadIdx.x;  // over Tt*Ff/4
    float4 gv = ((float4*)G)[i];
    float4 uv = ((const float4*)U)[i];
    gv.x = gv.x / (1.f + __expf(-gv.x)) * uv.x;
    gv.y = gv.y / (1.f + __expf(-gv.y)) * uv.y;
    gv.z = gv.z / (1.f + __expf(-gv.z)) * uv.z;
    gv.w = gv.w / (1.f + __expf(-gv.w)) * uv.w;
    ((float4*)G)[i] = gv;
}
__global__ __launch_bounds__(256) void act_expert(float* __restrict__ G, const float* __restrict__ U,
                                                  const float* __restrict__ M) {
    size_t i = (size_t)blockIdx.x * blockDim.x + threadIdx.x;  // over Tt*Ff/4
    size_t col4 = i & 1023;        // Ff/4 = 1024 float4 per row
    size_t t = i >> 10;
    int e = (int)(col4 >> 6);      // 64 float4 per expert chunk (FEe=256)
    float mk = M[t * Ee + e];
    float4 gv = ((float4*)G)[i];
    float4 uv = ((const float4*)U)[i];
    gv.x = mk * (gv.x / (1.f + __expf(-gv.x))) * uv.x;
    gv.y = mk * (gv.y / (1.f + __expf(-gv.y))) * uv.y;
    gv.z = mk * (gv.z / (1.f + __expf(-gv.z))) * uv.z;
    gv.w = mk * (gv.w / (1.f + __expf(-gv.w))) * uv.w;
    ((float4*)G)[i] = gv;
}

// ---------------- launch ----------------
extern "C" void kernel_launch(void* const* d_in, const int* in_sizes, int n_in,
                              void* d_out, int out_size) {
    const float* x     = (const float*)d_in[0];
    const float* emask = (const float*)d_in[1];
    const float* ln1   = (const float*)d_in[2];
    const float* wq    = (const float*)d_in[3];
    const float* bq    = (const float*)d_in[4];
    const float* wk    = (const float*)d_in[5];
    const float* bk    = (const float*)d_in[6];
    const float* wv    = (const float*)d_in[7];
    const float* bv    = (const float*)d_in[8];
    const float* wo    = (const float*)d_in[9];
    const float* ln2   = (const float*)d_in[10];
    const float* wgate = (const float*)d_in[11];
    const float* wup   = (const float*)d_in[12];
    const float* wdown = (const float*)d_in[13];
    const float* weg   = (const float*)d_in[14];
    const float* weu   = (const float*)d_in[15];
    const float* wed   = (const float*)d_in[16];
    float* out = (float*)d_out;

    float *h, *q, *k, *v, *o, *G1, *U1, *G2, *U2, *ct, *st;
    cudaGetSymbolAddress((void**)&h,  g_h);
    cudaGetSymbolAddress((void**)&q,  g_q);
    cudaGetSymbolAddress((void**)&k,  g_k);
    cudaGetSymbolAddress((void**)&v,  g_v);
    cudaGetSymbolAddress((void**)&o,  g_o);
    cudaGetSymbolAddress((void**)&G1, g_G1);
    cudaGetSymbolAddress((void**)&U1, g_U1);
    cudaGetSymbolAddress((void**)&G2, g_G2);
    cudaGetSymbolAddress((void**)&U2, g_U2);
    cudaGetSymbolAddress((void**)&ct, g_ct);
    cudaGetSymbolAddress((void**)&st, g_st);

    cudaFuncSetAttribute(gemm_tf32, cudaFuncAttributeMaxDynamicSharedMemorySize, GEMM_SMEM);
    cudaFuncSetAttribute(flash_attn, cudaFuncAttributeMaxDynamicSharedMemorySize, FLASH_SMEM);

    // 1) h = rmsnorm(x)
    rmsnorm_k<<<Tt, 256>>>(x, ln1, h);
    // 2) q,k,v projections (+bias)
    gemm_tf32<<<dim3(Dd / 128, Tt / 128), 256, GEMM_SMEM>>>(h, Dd, wq, Hh * HDh, 0, q, Hh * HDh, bq, nullptr, 0, Dd);
    gemm_tf32<<<dim3(512 / 128, Tt / 128), 256, GEMM_SMEM>>>(h, Dd, wk, KVh * HDh, 0, k, KVh * HDh, bk, nullptr, 0, Dd);
    gemm_tf32<<<dim3(512 / 128, Tt / 128), 256, GEMM_SMEM>>>(h, Dd, wv, KVh * HDh, 0, v, KVh * HDh, bv, nullptr, 0, Dd);
    // 3) RoPE
    rope_table<<<(Pp * 32) / 256, 256>>>(ct, st);
    rope_apply<<<(Tt * Hh * 32) / 256, 256>>>(q, ct, st, Hh);
    rope_apply<<<(Tt * KVh * 32) / 256, 256>>>(k, ct, st, KVh);
    // 4) causal GQA flash attention
    flash_attn<<<dim3(Pp / 128, Bb * Hh), 256, FLASH_SMEM>>>(q, k, v, o);
    // 5) out = o @ wo + x   (xo residual lives in d_out)
    gemm_tf32<<<dim3(Dd / 128, Tt / 128), 256, GEMM_SMEM>>>(o, Hh * HDh, wo, Dd, 0, out, Dd, nullptr, x, 0, Hh * HDh);
    // 6) h2 = rmsnorm(xo)
    rmsnorm_k<<<Tt, 256>>>(out, ln2, h);
    // 7) dense MLP + expert gate/up GEMMs
    gemm_tf32<<<dim3(Ff / 128, Tt / 128), 256, GEMM_SMEM>>>(h, Dd, wgate, Ff, 0, G1, Ff, nullptr, nullptr, 0, Dd);
    gemm_tf32<<<dim3(Ff / 128, Tt / 128), 256, GEMM_SMEM>>>(h, Dd, wup,   Ff, 0, U1, Ff, nullptr, nullptr, 0, Dd);
    gemm_tf32<<<dim3(Ff / 128, Tt / 128), 256, GEMM_SMEM>>>(h, Dd, weg, FEe, (size_t)Dd * FEe, G2, Ff, nullptr, nullptr, 0, Dd);
    gemm_tf32<<<dim3(Ff / 128, Tt / 128), 256, GEMM_SMEM>>>(h, Dd, weu, FEe, (size_t)Dd * FEe, U2, Ff, nullptr, nullptr, 0, Dd);
    // 8) activations (in-place into G1/G2; expert one folds the routing mask)
    act_base<<<((size_t)Tt * Ff / 4) / 256, 256>>>(G1, U1);
    act_expert<<<((size_t)Tt * Ff / 4) / 256, 256>>>(G2, U2, emask);
    // 9) out += act_b @ w_down ; out += act_e @ we_down_flat
    gemm_tf32<<<dim3(Dd / 128, Tt / 128), 256, GEMM_SMEM>>>(G1, Ff, wdown, Dd, 0, out, Dd, nullptr, nullptr, 1, Ff);
    gemm_tf32<<<dim3(Dd / 128, Tt / 128), 256, GEMM_SMEM>>>(G2, Ff, wed,   Dd, 0, out, Dd, nullptr, nullptr, 1, Ff);
}